// round 1
// baseline (speedup 1.0000x reference)
#include <cuda_runtime.h>
#include <cuda_bf16.h>
#include <math.h>

// Problem constants
#define BSZ 4
#define TT  4096
#define DD  2048
#define MR  (BSZ * TT)      // 16384 rows
#define LCH 64              // scan chunk length
#define NCH (TT / LCH)      // 64 chunks per sequence
#define ELEMS (MR * DD)     // 33,554,432

// ---------------- scratch (device globals; no allocation allowed) ----------
__device__ float g_iraw[ELEMS];   // i_raw  -> i (gated input)
__device__ float g_fraw[ELEMS];   // f_raw  -> a (forget gate)
__device__ float g_gbuf[ELEMS];   // g_raw
__device__ float g_obuf[ELEMS];   // scan output o
__device__ float g_P[BSZ * NCH * DD];
__device__ float g_S[BSZ * NCH * DD];
__device__ float g_H[BSZ * NCH * DD];

// ---------------- SGEMM: C[M,N] = A[M,K] * B[K,N], row-major, N=K=2048 -----
#define BM 128
#define BN 128
#define BK 8

__global__ __launch_bounds__(256, 2)
void sgemm_kernel(const float* __restrict__ A, const float* __restrict__ B,
                  float* __restrict__ C) {
    const int N = 2048, K = 2048;
    __shared__ float As[BK][BM];
    __shared__ float Bs[BK][BN];

    const int tid = threadIdx.x;
    const int bx = blockIdx.x;   // N tile
    const int by = blockIdx.y;   // M tile

    // A load: 128 rows x 8 k = 256 float4 (2 per row)
    const int aRow = tid >> 1;
    const int aK4  = (tid & 1) * 4;
    // B load: 8 k x 128 n = 256 float4
    const int bK   = tid >> 5;
    const int bN4  = (tid & 31) * 4;

    const float* Aptr = A + (long)(by * BM + aRow) * K + aK4;
    const float* Bptr = B + (long)bK * N + bx * BN + bN4;

    const int tx = tid & 15;
    const int ty = tid >> 4;

    float acc[8][8];
#pragma unroll
    for (int i = 0; i < 8; i++)
#pragma unroll
        for (int j = 0; j < 8; j++) acc[i][j] = 0.f;

    for (int k0 = 0; k0 < K; k0 += BK) {
        float4 av = *(const float4*)Aptr;  Aptr += BK;
        float4 bv = *(const float4*)Bptr;  Bptr += (long)BK * N;

        As[aK4 + 0][aRow] = av.x;
        As[aK4 + 1][aRow] = av.y;
        As[aK4 + 2][aRow] = av.z;
        As[aK4 + 3][aRow] = av.w;
        *(float4*)&Bs[bK][bN4] = bv;
        __syncthreads();

#pragma unroll
        for (int k = 0; k < BK; ++k) {
            float ra[8], rb[8];
            *(float4*)&ra[0] = *(const float4*)&As[k][ty * 8];
            *(float4*)&ra[4] = *(const float4*)&As[k][ty * 8 + 4];
            *(float4*)&rb[0] = *(const float4*)&Bs[k][tx * 8];
            *(float4*)&rb[4] = *(const float4*)&Bs[k][tx * 8 + 4];
#pragma unroll
            for (int i = 0; i < 8; i++)
#pragma unroll
                for (int j = 0; j < 8; j++)
                    acc[i][j] = fmaf(ra[i], rb[j], acc[i][j]);
        }
        __syncthreads();
    }

#pragma unroll
    for (int i = 0; i < 8; i++) {
        long row = (long)(by * BM + ty * 8 + i);
        float* cp = C + row * N + bx * BN + tx * 8;
        *(float4*)(cp + 0) = *(float4*)&acc[i][0];
        *(float4*)(cp + 4) = *(float4*)&acc[i][4];
    }
}

// ---------------- elementwise gates ----------------------------------------
// i = silu(i_raw) * sigmoid(-f_raw);  a = sigmoid(f_raw)
__global__ void gate_elem_kernel(float* __restrict__ iraw, float* __restrict__ fraw) {
    int idx = blockIdx.x * blockDim.x + threadIdx.x;
    if (idx >= ELEMS) return;
    float ir = iraw[idx];
    float fr = fraw[idx];
    float a      = 1.f / (1.f + expf(-fr));   // sigmoid(f)
    float signeg = 1.f / (1.f + expf(fr));    // sigmoid(-f)
    float si     = ir / (1.f + expf(-ir));    // silu(i_raw)
    iraw[idx] = si * signeg;
    fraw[idx] = a;
}

// ---------------- chunked scan ---------------------------------------------
// pass1: per (b, chunk, d): P = prod(a), S = scan value with h_in = 0
__global__ void scan_pass1_kernel(const float* __restrict__ a, const float* __restrict__ i,
                                  float* __restrict__ P, float* __restrict__ S) {
    int idx = blockIdx.x * blockDim.x + threadIdx.x;
    if (idx >= BSZ * NCH * DD) return;
    int d = idx % DD;
    int c = (idx / DD) % NCH;
    int b = idx / (DD * NCH);
    long base = ((long)(b * TT + c * LCH)) * DD + d;
    float h = 0.f, p = 1.f;
#pragma unroll 4
    for (int j = 0; j < LCH; j++) {
        float av = a[base + (long)j * DD];
        float iv = i[base + (long)j * DD];
        h = fmaf(av, h, iv);
        p *= av;
    }
    P[idx] = p;
    S[idx] = h;
}

// pass2: per (b, d): serial combine over chunks, record h_in per chunk
__global__ void scan_pass2_kernel(const float* __restrict__ P, const float* __restrict__ S,
                                  float* __restrict__ H) {
    int idx = blockIdx.x * blockDim.x + threadIdx.x;
    if (idx >= BSZ * DD) return;
    int d = idx % DD;
    int b = idx / DD;
    float h = 0.f;
#pragma unroll
    for (int c = 0; c < NCH; c++) {
        int s = (b * NCH + c) * DD + d;
        H[s] = h;
        h = fmaf(P[s], h, S[s]);
    }
}

// pass3: per (b, chunk, d): replay with known h_in, emit o[t]
__global__ void scan_pass3_kernel(const float* __restrict__ a, const float* __restrict__ i,
                                  const float* __restrict__ H, float* __restrict__ o) {
    int idx = blockIdx.x * blockDim.x + threadIdx.x;
    if (idx >= BSZ * NCH * DD) return;
    int d = idx % DD;
    int c = (idx / DD) % NCH;
    int b = idx / (DD * NCH);
    long base = ((long)(b * TT + c * LCH)) * DD + d;
    float h = H[idx];
#pragma unroll 4
    for (int j = 0; j < LCH; j++) {
        float av = a[base + (long)j * DD];
        float iv = i[base + (long)j * DD];
        h = fmaf(av, h, iv);
        o[base + (long)j * DD] = h;
    }
}

// ---------------- RMSNorm + swish gate -------------------------------------
// out = (o * rsqrt(mean(o^2)+eps) * gw) * (g * sigmoid(g))
__global__ __launch_bounds__(256)
void norm_gate_kernel(const float* __restrict__ o, const float* __restrict__ g,
                      const float* __restrict__ gw, float* __restrict__ out) {
    int r = blockIdx.x;
    int tid = threadIdx.x;
    __shared__ float red[256];

    const float* orow = o + (long)r * DD;
    float vals[8];
    float ss = 0.f;
#pragma unroll
    for (int j = 0; j < 8; j++) {
        float v = orow[tid + j * 256];
        vals[j] = v;
        ss = fmaf(v, v, ss);
    }
    red[tid] = ss;
    __syncthreads();
    for (int s = 128; s > 0; s >>= 1) {
        if (tid < s) red[tid] += red[tid + s];
        __syncthreads();
    }
    float rinv = rsqrtf(red[0] / (float)DD + 1e-5f);

    const float* grow = g + (long)r * DD;
    float* yrow = out + (long)r * DD;
#pragma unroll
    for (int j = 0; j < 8; j++) {
        int d = tid + j * 256;
        float gv = grow[d];
        float sw = gv / (1.f + expf(-gv));   // g * sigmoid(g)
        yrow[d] = (vals[j] * rinv * gw[d]) * sw;
    }
}

// ---------------- launch ----------------------------------------------------
extern "C" void kernel_launch(void* const* d_in, const int* in_sizes, int n_in,
                              void* d_out, int out_size) {
    const float* x  = (const float*)d_in[0];
    const float* Wi = (const float*)d_in[1];
    const float* Wf = (const float*)d_in[2];
    const float* Wg = (const float*)d_in[3];
    const float* Wo = (const float*)d_in[4];
    const float* gw = (const float*)d_in[5];
    float* out = (float*)d_out;

    float *p_iraw, *p_fraw, *p_gbuf, *p_obuf, *p_P, *p_S, *p_H;
    cudaGetSymbolAddress((void**)&p_iraw, g_iraw);
    cudaGetSymbolAddress((void**)&p_fraw, g_fraw);
    cudaGetSymbolAddress((void**)&p_gbuf, g_gbuf);
    cudaGetSymbolAddress((void**)&p_obuf, g_obuf);
    cudaGetSymbolAddress((void**)&p_P, g_P);
    cudaGetSymbolAddress((void**)&p_S, g_S);
    cudaGetSymbolAddress((void**)&p_H, g_H);

    dim3 gemmGrid(DD / BN, MR / BM);   // (16, 128)
    dim3 gemmBlock(256);

    // three input projections
    sgemm_kernel<<<gemmGrid, gemmBlock>>>(x, Wi, p_iraw);
    sgemm_kernel<<<gemmGrid, gemmBlock>>>(x, Wf, p_fraw);
    sgemm_kernel<<<gemmGrid, gemmBlock>>>(x, Wg, p_gbuf);

    // gates
    gate_elem_kernel<<<ELEMS / 256, 256>>>(p_iraw, p_fraw);

    // chunked linear-recurrence scan
    scan_pass1_kernel<<<(BSZ * NCH * DD) / 256, 256>>>(p_fraw, p_iraw, p_P, p_S);
    scan_pass2_kernel<<<(BSZ * DD) / 256, 256>>>(p_P, p_S, p_H);
    scan_pass3_kernel<<<(BSZ * NCH * DD) / 256, 256>>>(p_fraw, p_iraw, p_H, p_obuf);

    // RMSNorm * weight * swish(g)  (result reuses g_iraw)
    norm_gate_kernel<<<MR, 256>>>(p_obuf, p_gbuf, gw, p_iraw);

    // output projection
    sgemm_kernel<<<gemmGrid, gemmBlock>>>(p_iraw, Wo, out);
}

// round 3
// speedup vs baseline: 2.7736x; 2.7736x over previous
#include <cuda_runtime.h>
#include <cuda_fp16.h>
#include <math.h>
#include <stdint.h>

// Problem constants
#define BSZ 4
#define TT  4096
#define DD  2048
#define MR  (BSZ * TT)      // 16384 rows
#define LCH 64
#define NCH (TT / LCH)
#define ELEMS (MR * DD)
#define KT  6144            // split K: [hi | lo | hi]

// ---------------- scratch (device globals; no allocation allowed) ----------
__device__ float g_iraw[ELEMS];
__device__ float g_fraw[ELEMS];
__device__ float g_gbuf[ELEMS];
__device__ float g_obuf[ELEMS];
__device__ float g_P[BSZ * NCH * DD];
__device__ float g_S[BSZ * NCH * DD];
__device__ float g_H[BSZ * NCH * DD];
__device__ __half g_abuf[(size_t)MR * KT];        // activations (split)
__device__ __half g_wbuf[4][(size_t)DD * KT];     // weights (split, K-major)

// =================== PTX helpers ===========================================
__device__ __forceinline__ uint32_t smem_u32(const void* p) {
    uint32_t a;
    asm("{ .reg .u64 t; cvta.to.shared.u64 t, %1; cvt.u32.u64 %0, t; }" : "=r"(a) : "l"(p));
    return a;
}
__device__ __forceinline__ void cp_async16(uint32_t dst, const void* src) {
    asm volatile("cp.async.cg.shared.global [%0], [%1], 16;" :: "r"(dst), "l"(src) : "memory");
}
__device__ __forceinline__ void cp_commit() {
    asm volatile("cp.async.commit_group;" ::: "memory");
}
template <int N>
__device__ __forceinline__ void cp_wait() {
    asm volatile("cp.async.wait_group %0;" :: "n"(N) : "memory");
}
__device__ __forceinline__ void ldm_x4(uint32_t* r, uint32_t addr) {
    asm volatile("ldmatrix.sync.aligned.m8n8.x4.shared.b16 {%0,%1,%2,%3}, [%4];"
        : "=r"(r[0]), "=r"(r[1]), "=r"(r[2]), "=r"(r[3]) : "r"(addr));
}
__device__ __forceinline__ void mma16816(float* c, const uint32_t* a, const uint32_t* b) {
    asm volatile("mma.sync.aligned.m16n8k16.row.col.f32.f16.f16.f32 "
        "{%0,%1,%2,%3}, {%4,%5,%6,%7}, {%8,%9}, {%0,%1,%2,%3};"
        : "+f"(c[0]), "+f"(c[1]), "+f"(c[2]), "+f"(c[3])
        : "r"(a[0]), "r"(a[1]), "r"(a[2]), "r"(a[3]), "r"(b[0]), "r"(b[1]));
}

// =================== split-precision conversions ===========================
// activations: fp32 [M, 2048] -> fp16 [M, 6144] blocks [hi | lo | hi]
__global__ __launch_bounds__(256)
void convert_act_kernel(const float* __restrict__ in, __half* __restrict__ out) {
    size_t idx = ((size_t)blockIdx.x * blockDim.x + threadIdx.x) * 2;
    float2 v = *(const float2*)(in + idx);
    __half h0 = __float2half(v.x);
    __half h1 = __float2half(v.y);
    __half l0 = __float2half(v.x - __half2float(h0));
    __half l1 = __float2half(v.y - __half2float(h1));
    size_t row = idx >> 11;
    size_t col = idx & 2047;
    size_t ob = row * KT + col;
    __half2 hh; hh.x = h0; hh.y = h1;
    __half2 ll; ll.x = l0; ll.y = l1;
    *(__half2*)(out + ob)        = hh;
    *(__half2*)(out + ob + 2048) = ll;
    *(__half2*)(out + ob + 4096) = hh;
}

// weights: fp32 W[k, n] -> fp16 B[n, 6144] K-major, blocks [hi | hi | lo]
__global__ __launch_bounds__(256)
void convert_w_kernel(const float* __restrict__ W, __half* __restrict__ Bo) {
    __shared__ float ts[32][33];
    int n0 = blockIdx.x * 32, k0 = blockIdx.y * 32;
    int tx = threadIdx.x, ty = threadIdx.y;  // (32, 8)
#pragma unroll
    for (int i = 0; i < 4; i++)
        ts[ty + i * 8][tx] = W[(size_t)(k0 + ty + i * 8) * DD + n0 + tx];
    __syncthreads();
#pragma unroll
    for (int i = 0; i < 4; i++) {
        int n = n0 + ty + i * 8;
        float v = ts[tx][ty + i * 8];     // = W[k0+tx][n]
        __half hi = __float2half(v);
        __half lo = __float2half(v - __half2float(hi));
        size_t b = (size_t)n * KT + k0 + tx;
        Bo[b] = hi; Bo[b + 2048] = hi; Bo[b + 4096] = lo;
    }
}

// =================== mma.sync fp16 GEMM ====================================
// C[16384, 2048] = A[16384, 6144] x B[2048, 6144]^T (both K-major fp16), fp32 acc
#define BM 128
#define BN 128
#define BKE 32
#define GSTAGES 4
#define STAGE_A (BM * BKE * 2)              // 8192 B
#define STAGE_B (BN * BKE * 2)              // 8192 B
#define STAGE_BYTES (STAGE_A + STAGE_B)     // 16384
#define GEMM_SMEM (GSTAGES * STAGE_BYTES)   // 64 KB
#define KTILES (KT / BKE)                   // 192

// swizzled smem offset for a 16B chunk: row has 4 chunks (64B)
__device__ __forceinline__ uint32_t swz(int row, int ch) {
    return (uint32_t)(row * 64 + ((ch ^ ((row >> 1) & 3)) << 4));
}

__global__ __launch_bounds__(256)
void gemm_mma_kernel(const __half* __restrict__ A, const __half* __restrict__ B,
                     float* __restrict__ C) {
    extern __shared__ char smem[];
    const uint32_t sb = smem_u32(smem);
    const int tid = threadIdx.x;
    const int lane = tid & 31;
    const int wid = tid >> 5;
    const int wm = wid & 1;       // 2 warps over M: 64 rows each
    const int wn = wid >> 1;      // 4 warps over N: 32 cols each

    // global load coords (per thread: 2 A chunks + 2 B chunks of 16B)
    const __half* gA = A + (size_t)blockIdx.y * BM * KT;
    const __half* gB = B + (size_t)blockIdx.x * BN * KT;

    // precomputed smem fragment read offsets (within a stage)
    uint32_t aof[2][4], bof[2][2];
#pragma unroll
    for (int ks = 0; ks < 2; ks++) {
#pragma unroll
        for (int mf = 0; mf < 4; mf++) {
            int r = wm * 64 + mf * 16 + (lane & 15);
            int ch = ks * 2 + (lane >> 4);
            aof[ks][mf] = swz(r, ch);
        }
#pragma unroll
        for (int p = 0; p < 2; p++) {
            int r = wn * 32 + p * 16 + (lane & 7) + ((lane >> 4) << 3);
            int ch = ks * 2 + ((lane >> 3) & 1);
            bof[ks][p] = STAGE_A + swz(r, ch);
        }
    }

    float acc[4][4][4];
#pragma unroll
    for (int i = 0; i < 4; i++)
#pragma unroll
        for (int j = 0; j < 4; j++)
#pragma unroll
            for (int q = 0; q < 4; q++) acc[i][j][q] = 0.f;

    // tile loader
    auto load_tile = [&](int kt) {
        uint32_t st = sb + (uint32_t)(kt & 3) * STAGE_BYTES;
        size_t koff = (size_t)kt * BKE;
#pragma unroll
        for (int h = 0; h < 2; h++) {
            int id = tid + h * 256;
            int row = id >> 2, ch = id & 3;
            cp_async16(st + swz(row, ch), gA + (size_t)row * KT + koff + ch * 8);
        }
#pragma unroll
        for (int h = 0; h < 2; h++) {
            int id = tid + h * 256;
            int row = id >> 2, ch = id & 3;
            cp_async16(st + STAGE_A + swz(row, ch), gB + (size_t)row * KT + koff + ch * 8);
        }
    };

    // prologue: stages 0..2
    load_tile(0); cp_commit();
    load_tile(1); cp_commit();
    load_tile(2); cp_commit();

#pragma unroll 1
    for (int kt = 0; kt < KTILES; ++kt) {
        cp_wait<2>();
        __syncthreads();
        if (kt + 3 < KTILES) load_tile(kt + 3);
        cp_commit();

        uint32_t st = sb + (uint32_t)(kt & 3) * STAGE_BYTES;
#pragma unroll
        for (int ks = 0; ks < 2; ks++) {
            uint32_t ar[4][4], br[2][4];
#pragma unroll
            for (int mf = 0; mf < 4; mf++) ldm_x4(ar[mf], st + aof[ks][mf]);
#pragma unroll
            for (int p = 0; p < 2; p++) ldm_x4(br[p], st + bof[ks][p]);
#pragma unroll
            for (int mf = 0; mf < 4; mf++)
#pragma unroll
                for (int nf = 0; nf < 4; nf++)
                    mma16816(acc[mf][nf], ar[mf], &br[nf >> 1][(nf & 1) * 2]);
        }
    }

    // epilogue
#pragma unroll
    for (int mf = 0; mf < 4; mf++) {
#pragma unroll
        for (int nf = 0; nf < 4; nf++) {
            int row = blockIdx.y * BM + wm * 64 + mf * 16 + (lane >> 2);
            int col = blockIdx.x * BN + wn * 32 + nf * 8 + (lane & 3) * 2;
            float2 v0; v0.x = acc[mf][nf][0]; v0.y = acc[mf][nf][1];
            float2 v1; v1.x = acc[mf][nf][2]; v1.y = acc[mf][nf][3];
            *(float2*)(C + (size_t)row * DD + col) = v0;
            *(float2*)(C + (size_t)(row + 8) * DD + col) = v1;
        }
    }
}

// ---------------- elementwise gates ----------------------------------------
__global__ void gate_elem_kernel(float* __restrict__ iraw, float* __restrict__ fraw) {
    int idx = blockIdx.x * blockDim.x + threadIdx.x;
    float ir = iraw[idx];
    float fr = fraw[idx];
    float a      = 1.f / (1.f + expf(-fr));
    float signeg = 1.f / (1.f + expf(fr));
    float si     = ir / (1.f + expf(-ir));
    iraw[idx] = si * signeg;
    fraw[idx] = a;
}

// ---------------- chunked scan ---------------------------------------------
__global__ void scan_pass1_kernel(const float* __restrict__ a, const float* __restrict__ i,
                                  float* __restrict__ P, float* __restrict__ S) {
    int idx = blockIdx.x * blockDim.x + threadIdx.x;
    int d = idx % DD;
    int c = (idx / DD) % NCH;
    int b = idx / (DD * NCH);
    size_t base = ((size_t)(b * TT + c * LCH)) * DD + d;
    float h = 0.f, p = 1.f;
#pragma unroll 4
    for (int j = 0; j < LCH; j++) {
        float av = a[base + (size_t)j * DD];
        float iv = i[base + (size_t)j * DD];
        h = fmaf(av, h, iv);
        p *= av;
    }
    P[idx] = p;
    S[idx] = h;
}

__global__ void scan_pass2_kernel(const float* __restrict__ P, const float* __restrict__ S,
                                  float* __restrict__ H) {
    int idx = blockIdx.x * blockDim.x + threadIdx.x;
    int d = idx % DD;
    int b = idx / DD;
    float h = 0.f;
#pragma unroll
    for (int c = 0; c < NCH; c++) {
        int s = (b * NCH + c) * DD + d;
        H[s] = h;
        h = fmaf(P[s], h, S[s]);
    }
}

__global__ void scan_pass3_kernel(const float* __restrict__ a, const float* __restrict__ i,
                                  const float* __restrict__ H, float* __restrict__ o) {
    int idx = blockIdx.x * blockDim.x + threadIdx.x;
    int d = idx % DD;
    int c = (idx / DD) % NCH;
    int b = idx / (DD * NCH);
    size_t base = ((size_t)(b * TT + c * LCH)) * DD + d;
    float h = H[idx];
#pragma unroll 4
    for (int j = 0; j < LCH; j++) {
        float av = a[base + (size_t)j * DD];
        float iv = i[base + (size_t)j * DD];
        h = fmaf(av, h, iv);
        o[base + (size_t)j * DD] = h;
    }
}

// ---------------- RMSNorm + swish gate -------------------------------------
__global__ __launch_bounds__(256)
void norm_gate_kernel(const float* __restrict__ o, const float* __restrict__ g,
                      const float* __restrict__ gw, float* __restrict__ out) {
    int r = blockIdx.x;
    int tid = threadIdx.x;
    __shared__ float red[256];

    const float* orow = o + (size_t)r * DD;
    float vals[8];
    float ss = 0.f;
#pragma unroll
    for (int j = 0; j < 8; j++) {
        float v = orow[tid + j * 256];
        vals[j] = v;
        ss = fmaf(v, v, ss);
    }
    red[tid] = ss;
    __syncthreads();
    for (int s = 128; s > 0; s >>= 1) {
        if (tid < s) red[tid] += red[tid + s];
        __syncthreads();
    }
    float rinv = rsqrtf(red[0] / (float)DD + 1e-5f);

    const float* grow = g + (size_t)r * DD;
    float* yrow = out + (size_t)r * DD;
#pragma unroll
    for (int j = 0; j < 8; j++) {
        int d = tid + j * 256;
        float gv = grow[d];
        float sw = gv / (1.f + expf(-gv));
        yrow[d] = (vals[j] * rinv * gw[d]) * sw;
    }
}

// ---------------- launch ----------------------------------------------------
extern "C" void kernel_launch(void* const* d_in, const int* in_sizes, int n_in,
                              void* d_out, int out_size) {
    const float* x  = (const float*)d_in[0];
    const float* Wi = (const float*)d_in[1];
    const float* Wf = (const float*)d_in[2];
    const float* Wg = (const float*)d_in[3];
    const float* Wo = (const float*)d_in[4];
    const float* gw = (const float*)d_in[5];
    float* out = (float*)d_out;

    float *p_iraw, *p_fraw, *p_gbuf, *p_obuf, *p_P, *p_S, *p_H;
    __half *p_abuf, *p_wbuf;
    cudaGetSymbolAddress((void**)&p_iraw, g_iraw);
    cudaGetSymbolAddress((void**)&p_fraw, g_fraw);
    cudaGetSymbolAddress((void**)&p_gbuf, g_gbuf);
    cudaGetSymbolAddress((void**)&p_obuf, g_obuf);
    cudaGetSymbolAddress((void**)&p_P, g_P);
    cudaGetSymbolAddress((void**)&p_S, g_S);
    cudaGetSymbolAddress((void**)&p_H, g_H);
    cudaGetSymbolAddress((void**)&p_abuf, g_abuf);
    cudaGetSymbolAddress((void**)&p_wbuf, g_wbuf);
    __half* pw[4];
    for (int i = 0; i < 4; i++) pw[i] = p_wbuf + (size_t)i * DD * KT;

    cudaFuncSetAttribute(gemm_mma_kernel,
                         cudaFuncAttributeMaxDynamicSharedMemorySize, GEMM_SMEM);

    dim3 wgrid(DD / 32, DD / 32), wblock(32, 8);
    convert_w_kernel<<<wgrid, wblock>>>(Wi, pw[0]);
    convert_w_kernel<<<wgrid, wblock>>>(Wf, pw[1]);
    convert_w_kernel<<<wgrid, wblock>>>(Wg, pw[2]);
    convert_w_kernel<<<wgrid, wblock>>>(Wo, pw[3]);
    convert_act_kernel<<<ELEMS / 512, 256>>>(x, p_abuf);

    dim3 ggrid(DD / BN, MR / BM);  // (16, 128)
    gemm_mma_kernel<<<ggrid, 256, GEMM_SMEM>>>(p_abuf, pw[0], p_iraw);
    gemm_mma_kernel<<<ggrid, 256, GEMM_SMEM>>>(p_abuf, pw[1], p_fraw);
    gemm_mma_kernel<<<ggrid, 256, GEMM_SMEM>>>(p_abuf, pw[2], p_gbuf);

    gate_elem_kernel<<<ELEMS / 256, 256>>>(p_iraw, p_fraw);

    scan_pass1_kernel<<<(BSZ * NCH * DD) / 256, 256>>>(p_fraw, p_iraw, p_P, p_S);
    scan_pass2_kernel<<<(BSZ * DD) / 256, 256>>>(p_P, p_S, p_H);
    scan_pass3_kernel<<<(BSZ * NCH * DD) / 256, 256>>>(p_fraw, p_iraw, p_H, p_obuf);

    norm_gate_kernel<<<MR, 256>>>(p_obuf, p_gbuf, gw, p_iraw);

    convert_act_kernel<<<ELEMS / 512, 256>>>(p_iraw, p_abuf);
    gemm_mma_kernel<<<ggrid, 256, GEMM_SMEM>>>(p_abuf, pw[3], out);
}

// round 4
// speedup vs baseline: 4.1157x; 1.4839x over previous
#include <cuda_runtime.h>
#include <cuda_fp16.h>
#include <math.h>
#include <stdint.h>

// Problem constants
#define BSZ 4
#define TT  4096
#define DD  2048
#define MR  (BSZ * TT)      // 16384 rows
#define LCH 64
#define NCH (TT / LCH)
#define ELEMS (MR * DD)
#define KT  4096            // split K: A=[hi|lo], B=[hi|hi]

// ---------------- scratch (device globals; no allocation allowed) ----------
__device__ float g_iraw[ELEMS];
__device__ float g_fraw[ELEMS];
__device__ float g_gbuf[ELEMS];
__device__ float g_obuf[ELEMS];
__device__ float g_P[BSZ * NCH * DD];
__device__ float g_S[BSZ * NCH * DD];
__device__ float g_H[BSZ * NCH * DD];
__device__ __half g_abuf[(size_t)MR * KT];        // activations (hi|lo)
__device__ __half g_wbuf[4][(size_t)DD * KT];     // weights (hi|hi), K-major

// =================== PTX helpers ===========================================
__device__ __forceinline__ uint32_t smem_u32(const void* p) {
    uint32_t a;
    asm("{ .reg .u64 t; cvta.to.shared.u64 t, %1; cvt.u32.u64 %0, t; }" : "=r"(a) : "l"(p));
    return a;
}
__device__ __forceinline__ void cp_async16(uint32_t dst, const void* src) {
    asm volatile("cp.async.cg.shared.global [%0], [%1], 16;" :: "r"(dst), "l"(src) : "memory");
}
__device__ __forceinline__ void cp_commit() {
    asm volatile("cp.async.commit_group;" ::: "memory");
}
template <int N>
__device__ __forceinline__ void cp_wait() {
    asm volatile("cp.async.wait_group %0;" :: "n"(N) : "memory");
}
__device__ __forceinline__ void ldm_x4(uint32_t* r, uint32_t addr) {
    asm volatile("ldmatrix.sync.aligned.m8n8.x4.shared.b16 {%0,%1,%2,%3}, [%4];"
        : "=r"(r[0]), "=r"(r[1]), "=r"(r[2]), "=r"(r[3]) : "r"(addr));
}
__device__ __forceinline__ void mma16816(float* c, const uint32_t* a, const uint32_t* b) {
    asm volatile("mma.sync.aligned.m16n8k16.row.col.f32.f16.f16.f32 "
        "{%0,%1,%2,%3}, {%4,%5,%6,%7}, {%8,%9}, {%0,%1,%2,%3};"
        : "+f"(c[0]), "+f"(c[1]), "+f"(c[2]), "+f"(c[3])
        : "r"(a[0]), "r"(a[1]), "r"(a[2]), "r"(a[3]), "r"(b[0]), "r"(b[1]));
}

// =================== split-precision conversions ===========================
// activations: fp32 [M, 2048] -> fp16 [M, 4096] blocks [hi | lo]
__global__ __launch_bounds__(256)
void convert_act_kernel(const float* __restrict__ in, __half* __restrict__ out) {
    size_t idx = ((size_t)blockIdx.x * blockDim.x + threadIdx.x) * 2;
    float2 v = *(const float2*)(in + idx);
    __half h0 = __float2half(v.x);
    __half h1 = __float2half(v.y);
    __half l0 = __float2half(v.x - __half2float(h0));
    __half l1 = __float2half(v.y - __half2float(h1));
    size_t row = idx >> 11;
    size_t col = idx & 2047;
    size_t ob = row * KT + col;
    __half2 hh; hh.x = h0; hh.y = h1;
    __half2 ll; ll.x = l0; ll.y = l1;
    *(__half2*)(out + ob)        = hh;
    *(__half2*)(out + ob + 2048) = ll;
}

// weights: fp32 W[k, n] -> fp16 B[n, 4096] K-major, blocks [hi | hi]
__global__ __launch_bounds__(256)
void convert_w_kernel(const float* __restrict__ W, __half* __restrict__ Bo) {
    __shared__ float ts[32][33];
    int n0 = blockIdx.x * 32, k0 = blockIdx.y * 32;
    int tx = threadIdx.x, ty = threadIdx.y;  // (32, 8)
#pragma unroll
    for (int i = 0; i < 4; i++)
        ts[ty + i * 8][tx] = W[(size_t)(k0 + ty + i * 8) * DD + n0 + tx];
    __syncthreads();
#pragma unroll
    for (int i = 0; i < 4; i++) {
        int n = n0 + ty + i * 8;
        float v = ts[tx][ty + i * 8];     // = W[k0+tx][n]
        __half hi = __float2half(v);
        size_t b = (size_t)n * KT + k0 + tx;
        Bo[b] = hi; Bo[b + 2048] = hi;
    }
}

// =================== mma.sync fp16 GEMM ====================================
// C[16384, 2048] = A[16384, 4096] x B[2048, 4096]^T (both K-major fp16), fp32 acc
#define BM 128
#define BN 128
#define BKE 32
#define GSTAGES 4
#define STAGE_A (BM * BKE * 2)              // 8192 B
#define STAGE_B (BN * BKE * 2)              // 8192 B
#define STAGE_BYTES (STAGE_A + STAGE_B)     // 16384
#define GEMM_SMEM (GSTAGES * STAGE_BYTES)   // 64 KB
#define KTILES (KT / BKE)                   // 128

// swizzled smem offset for a 16B chunk: row has 4 chunks (64B)
__device__ __forceinline__ uint32_t swz(int row, int ch) {
    return (uint32_t)(row * 64 + ((ch ^ ((row >> 1) & 3)) << 4));
}

__global__ __launch_bounds__(256)
void gemm_mma_kernel(const __half* __restrict__ A, const __half* __restrict__ B,
                     float* __restrict__ C) {
    extern __shared__ char smem[];
    const uint32_t sb = smem_u32(smem);
    const int tid = threadIdx.x;
    const int lane = tid & 31;
    const int wid = tid >> 5;
    const int wm = wid & 1;       // 2 warps over M: 64 rows each
    const int wn = wid >> 1;      // 4 warps over N: 32 cols each

    const __half* gA = A + (size_t)blockIdx.y * BM * KT;
    const __half* gB = B + (size_t)blockIdx.x * BN * KT;

    uint32_t aof[2][4], bof[2][2];
#pragma unroll
    for (int ks = 0; ks < 2; ks++) {
#pragma unroll
        for (int mf = 0; mf < 4; mf++) {
            int r = wm * 64 + mf * 16 + (lane & 15);
            int ch = ks * 2 + (lane >> 4);
            aof[ks][mf] = swz(r, ch);
        }
#pragma unroll
        for (int p = 0; p < 2; p++) {
            int r = wn * 32 + p * 16 + (lane & 7) + ((lane >> 4) << 3);
            int ch = ks * 2 + ((lane >> 3) & 1);
            bof[ks][p] = STAGE_A + swz(r, ch);
        }
    }

    float acc[4][4][4];
#pragma unroll
    for (int i = 0; i < 4; i++)
#pragma unroll
        for (int j = 0; j < 4; j++)
#pragma unroll
            for (int q = 0; q < 4; q++) acc[i][j][q] = 0.f;

    auto load_tile = [&](int kt) {
        uint32_t st = sb + (uint32_t)(kt & 3) * STAGE_BYTES;
        size_t koff = (size_t)kt * BKE;
#pragma unroll
        for (int h = 0; h < 2; h++) {
            int id = tid + h * 256;
            int row = id >> 2, ch = id & 3;
            cp_async16(st + swz(row, ch), gA + (size_t)row * KT + koff + ch * 8);
        }
#pragma unroll
        for (int h = 0; h < 2; h++) {
            int id = tid + h * 256;
            int row = id >> 2, ch = id & 3;
            cp_async16(st + STAGE_A + swz(row, ch), gB + (size_t)row * KT + koff + ch * 8);
        }
    };

    load_tile(0); cp_commit();
    load_tile(1); cp_commit();
    load_tile(2); cp_commit();

#pragma unroll 1
    for (int kt = 0; kt < KTILES; ++kt) {
        cp_wait<2>();
        __syncthreads();
        if (kt + 3 < KTILES) load_tile(kt + 3);
        cp_commit();

        uint32_t st = sb + (uint32_t)(kt & 3) * STAGE_BYTES;
#pragma unroll
        for (int ks = 0; ks < 2; ks++) {
            uint32_t ar[4][4], br[2][4];
#pragma unroll
            for (int mf = 0; mf < 4; mf++) ldm_x4(ar[mf], st + aof[ks][mf]);
#pragma unroll
            for (int p = 0; p < 2; p++) ldm_x4(br[p], st + bof[ks][p]);
#pragma unroll
            for (int mf = 0; mf < 4; mf++)
#pragma unroll
                for (int nf = 0; nf < 4; nf++)
                    mma16816(acc[mf][nf], ar[mf], &br[nf >> 1][(nf & 1) * 2]);
        }
    }

    // epilogue
#pragma unroll
    for (int mf = 0; mf < 4; mf++) {
#pragma unroll
        for (int nf = 0; nf < 4; nf++) {
            int row = blockIdx.y * BM + wm * 64 + mf * 16 + (lane >> 2);
            int col = blockIdx.x * BN + wn * 32 + nf * 8 + (lane & 3) * 2;
            float2 v0; v0.x = acc[mf][nf][0]; v0.y = acc[mf][nf][1];
            float2 v1; v1.x = acc[mf][nf][2]; v1.y = acc[mf][nf][3];
            *(float2*)(C + (size_t)row * DD + col) = v0;
            *(float2*)(C + (size_t)(row + 8) * DD + col) = v1;
        }
    }
}

// ---------------- chunked scan with fused gates ----------------------------
// from raw GEMM outputs: a = sigmoid(f_raw); i = silu(i_raw) * (1 - a)
__device__ __forceinline__ void gate_pair(float ir, float fr, float& a, float& i) {
    a = 1.f / (1.f + expf(-fr));
    float si = ir / (1.f + expf(-ir));
    i = si * (1.f - a);
}

__global__ void scan_pass1_kernel(const float* __restrict__ fraw, const float* __restrict__ iraw,
                                  float* __restrict__ P, float* __restrict__ S) {
    int idx = blockIdx.x * blockDim.x + threadIdx.x;
    int d = idx % DD;
    int c = (idx / DD) % NCH;
    int b = idx / (DD * NCH);
    size_t base = ((size_t)(b * TT + c * LCH)) * DD + d;
    float h = 0.f, p = 1.f;
#pragma unroll 4
    for (int j = 0; j < LCH; j++) {
        float a, iv;
        gate_pair(iraw[base + (size_t)j * DD], fraw[base + (size_t)j * DD], a, iv);
        h = fmaf(a, h, iv);
        p *= a;
    }
    P[idx] = p;
    S[idx] = h;
}

__global__ void scan_pass2_kernel(const float* __restrict__ P, const float* __restrict__ S,
                                  float* __restrict__ H) {
    int idx = blockIdx.x * blockDim.x + threadIdx.x;
    int d = idx % DD;
    int b = idx / DD;
    float h = 0.f;
#pragma unroll
    for (int c = 0; c < NCH; c++) {
        int s = (b * NCH + c) * DD + d;
        H[s] = h;
        h = fmaf(P[s], h, S[s]);
    }
}

__global__ void scan_pass3_kernel(const float* __restrict__ fraw, const float* __restrict__ iraw,
                                  const float* __restrict__ H, float* __restrict__ o) {
    int idx = blockIdx.x * blockDim.x + threadIdx.x;
    int d = idx % DD;
    int c = (idx / DD) % NCH;
    int b = idx / (DD * NCH);
    size_t base = ((size_t)(b * TT + c * LCH)) * DD + d;
    float h = H[idx];
#pragma unroll 4
    for (int j = 0; j < LCH; j++) {
        float a, iv;
        gate_pair(iraw[base + (size_t)j * DD], fraw[base + (size_t)j * DD], a, iv);
        h = fmaf(a, h, iv);
        o[base + (size_t)j * DD] = h;
    }
}

// ---------------- RMSNorm + swish gate + fp16 split convert ----------------
// y = (o * rsqrt(mean(o^2)+eps) * gw) * (g * sigmoid(g)); write [hi|lo] fp16
__global__ __launch_bounds__(256)
void norm_gate_convert_kernel(const float* __restrict__ o, const float* __restrict__ g,
                              const float* __restrict__ gw, __half* __restrict__ out) {
    int r = blockIdx.x;
    int tid = threadIdx.x;
    __shared__ float red[256];

    const float* orow = o + (size_t)r * DD;
    float vals[8];
    float ss = 0.f;
#pragma unroll
    for (int j = 0; j < 8; j++) {
        float v = orow[tid + j * 256];
        vals[j] = v;
        ss = fmaf(v, v, ss);
    }
    red[tid] = ss;
    __syncthreads();
    for (int s = 128; s > 0; s >>= 1) {
        if (tid < s) red[tid] += red[tid + s];
        __syncthreads();
    }
    float rinv = rsqrtf(red[0] / (float)DD + 1e-5f);

    const float* grow = g + (size_t)r * DD;
    __half* yrow = out + (size_t)r * KT;
#pragma unroll
    for (int j = 0; j < 8; j++) {
        int d = tid + j * 256;
        float gv = grow[d];
        float sw = gv / (1.f + expf(-gv));
        float y = (vals[j] * rinv * gw[d]) * sw;
        __half hi = __float2half(y);
        __half lo = __float2half(y - __half2float(hi));
        yrow[d] = hi;
        yrow[d + 2048] = lo;
    }
}

// ---------------- launch ----------------------------------------------------
extern "C" void kernel_launch(void* const* d_in, const int* in_sizes, int n_in,
                              void* d_out, int out_size) {
    const float* x  = (const float*)d_in[0];
    const float* Wi = (const float*)d_in[1];
    const float* Wf = (const float*)d_in[2];
    const float* Wg = (const float*)d_in[3];
    const float* Wo = (const float*)d_in[4];
    const float* gw = (const float*)d_in[5];
    float* out = (float*)d_out;

    float *p_iraw, *p_fraw, *p_gbuf, *p_obuf, *p_P, *p_S, *p_H;
    __half *p_abuf, *p_wbuf;
    cudaGetSymbolAddress((void**)&p_iraw, g_iraw);
    cudaGetSymbolAddress((void**)&p_fraw, g_fraw);
    cudaGetSymbolAddress((void**)&p_gbuf, g_gbuf);
    cudaGetSymbolAddress((void**)&p_obuf, g_obuf);
    cudaGetSymbolAddress((void**)&p_P, g_P);
    cudaGetSymbolAddress((void**)&p_S, g_S);
    cudaGetSymbolAddress((void**)&p_H, g_H);
    cudaGetSymbolAddress((void**)&p_abuf, g_abuf);
    cudaGetSymbolAddress((void**)&p_wbuf, g_wbuf);
    __half* pw[4];
    for (int i = 0; i < 4; i++) pw[i] = p_wbuf + (size_t)i * DD * KT;

    cudaFuncSetAttribute(gemm_mma_kernel,
                         cudaFuncAttributeMaxDynamicSharedMemorySize, GEMM_SMEM);

    dim3 wgrid(DD / 32, DD / 32), wblock(32, 8);
    convert_w_kernel<<<wgrid, wblock>>>(Wi, pw[0]);
    convert_w_kernel<<<wgrid, wblock>>>(Wf, pw[1]);
    convert_w_kernel<<<wgrid, wblock>>>(Wg, pw[2]);
    convert_w_kernel<<<wgrid, wblock>>>(Wo, pw[3]);
    convert_act_kernel<<<ELEMS / 512, 256>>>(x, p_abuf);

    dim3 ggrid(DD / BN, MR / BM);  // (16, 128)
    gemm_mma_kernel<<<ggrid, 256, GEMM_SMEM>>>(p_abuf, pw[0], p_iraw);
    gemm_mma_kernel<<<ggrid, 256, GEMM_SMEM>>>(p_abuf, pw[1], p_fraw);
    gemm_mma_kernel<<<ggrid, 256, GEMM_SMEM>>>(p_abuf, pw[2], p_gbuf);

    scan_pass1_kernel<<<(BSZ * NCH * DD) / 256, 256>>>(p_fraw, p_iraw, p_P, p_S);
    scan_pass2_kernel<<<(BSZ * DD) / 256, 256>>>(p_P, p_S, p_H);
    scan_pass3_kernel<<<(BSZ * NCH * DD) / 256, 256>>>(p_fraw, p_iraw, p_H, p_obuf);

    norm_gate_convert_kernel<<<MR, 256>>>(p_obuf, p_gbuf, gw, p_abuf);

    gemm_mma_kernel<<<ggrid, 256, GEMM_SMEM>>>(p_abuf, pw[3], out);
}